// round 9
// baseline (speedup 1.0000x reference)
#include <cuda_runtime.h>
#include <cstdint>

#define Bb 256
#define Tt 512
typedef unsigned long long ull;

__device__ uint2 g_keys[1024];
__device__ float g_gum[1024][2560];
__device__ int   g_act2[Tt * Bb];
__device__ float g_gi[(size_t)Bb * Tt * 384];

__device__ __forceinline__ void tf2x32(uint32_t k0, uint32_t k1,
                                       uint32_t x0, uint32_t x1,
                                       uint32_t &o0, uint32_t &o1) {
  uint32_t k2 = k0 ^ k1 ^ 0x1BD11BDAu;
#define R_(r) { x0 += x1; x1 = (x1 << (r)) | (x1 >> (32 - (r))); x1 ^= x0; }
  x0 += k0; x1 += k1;
  R_(13) R_(15) R_(26) R_(6)  x0 += k1; x1 += k2 + 1u;
  R_(17) R_(29) R_(16) R_(24) x0 += k2; x1 += k0 + 2u;
  R_(13) R_(15) R_(26) R_(6)  x0 += k0; x1 += k1 + 3u;
  R_(17) R_(29) R_(16) R_(24) x0 += k1; x1 += k2 + 4u;
  R_(13) R_(15) R_(26) R_(6)  x0 += k2; x1 += k0 + 5u;
#undef R_
  o0 = x0; o1 = x1;
}

__device__ __forceinline__ float b2g(uint32_t bits) {
  float f = __uint_as_float((bits >> 9) | 0x3f800000u) - 1.0f;
  float u = fmaxf(f, 1.17549435e-38f);
  return -logf(-logf(u));
}

__device__ __forceinline__ float sigm(float x) { return 1.0f / (1.0f + expf(-x)); }

__device__ __forceinline__ void f2(ull &c, ull a, ull b) {
  asm("fma.rn.f32x2 %0, %1, %2, %0;" : "+l"(c) : "l"(a), "l"(b));
}
__device__ __forceinline__ float hsum(ull a) {
  return __uint_as_float((unsigned)a) + __uint_as_float((unsigned)(a >> 32));
}

__global__ void k_keys() {
  int j = blockIdx.x * 256 + threadIdx.x;
  if (j >= 1024) return;
  uint32_t o0, o1;
  tf2x32(0u, 42u, 0u, (uint32_t)j, o0, o1);
  g_keys[j] = make_uint2(o0, o1);
}

__global__ void k_gum() {
  int j = blockIdx.x;
  uint2 key = g_keys[j];
  for (int p = threadIdx.x; p < 2560; p += 256) {
    uint32_t o0, o1;
    tf2x32(key.x, key.y, 0u, (uint32_t)p, o0, o1);
    g_gum[j][p] = b2g(o0 ^ o1);
  }
}

// gi GEMM: grid (1024,3), 256 thr, x full in smem, W streamed as 32-k panels.
__global__ __launch_bounds__(256, 2) void k_gi(const float* __restrict__ x,
                                               const float* __restrict__ wih,
                                               const float* __restrict__ bih,
                                               const float* __restrict__ bhh) {
  extern __shared__ float sm[];
  float* xs = sm;              // 128 x 132
  float* wp = sm + 128 * 132;  // 2 panels x 32 x 132 (k-major)
  int tid = threadIdx.x;
  size_t m0 = (size_t)blockIdx.x * 128;
  int n0 = blockIdx.y * 128;
  int mr = tid >> 1, hl = tid & 1;
  {
    const float4* src = (const float4*)(x + (m0 + mr) * 128 + hl * 64);
    float4* dst = (float4*)(xs + mr * 132 + hl * 64);
#pragma unroll
    for (int i = 0; i < 16; i++) dst[i] = src[i];
  }
  int rn = tid & 127, kh = (tid >> 7) * 16;   // row, local-k offset {0,16}
  float4 stage[4];
  {
    const float4* src = (const float4*)(wih + (size_t)(n0 + rn) * 128 + kh);
#pragma unroll
    for (int j = 0; j < 4; j++) stage[j] = src[j];
#pragma unroll
    for (int j = 0; j < 4; j++) {
      int kb = kh + 4 * j;
      wp[(kb+0)*132+rn] = stage[j].x; wp[(kb+1)*132+rn] = stage[j].y;
      wp[(kb+2)*132+rn] = stage[j].z; wp[(kb+3)*132+rn] = stage[j].w;
    }
  }
  int tx = tid & 15, ty = tid >> 4;
  float bv[8];
#pragma unroll
  for (int j = 0; j < 8; j++) {
    int g = n0 + tx * 8 + j;
    bv[j] = bih[g] + (g < 256 ? bhh[g] : 0.0f);
  }
  __syncthreads();

  float acc[64];
#pragma unroll
  for (int i = 0; i < 8; i++)
#pragma unroll
    for (int j = 0; j < 8; j++) acc[i * 8 + j] = bv[j];
  const float* xrow = xs + ty * 8 * 132;

#pragma unroll
  for (int p = 0; p < 4; p++) {
    if (p < 3) {
      const float4* src = (const float4*)(wih + (size_t)(n0 + rn) * 128 + 32 * (p + 1) + kh);
#pragma unroll
      for (int j = 0; j < 4; j++) stage[j] = src[j];
    }
    const float* wb = wp + (p & 1) * 4224;
    const float* xp = xrow + p * 32;
#pragma unroll
    for (int kk = 0; kk < 32; kk += 4) {
      float4 a4[8];
#pragma unroll
      for (int i = 0; i < 8; i++) a4[i] = *(const float4*)(xp + i * 132 + kk);
#pragma unroll
      for (int dk = 0; dk < 4; dk++) {
        float4 bl = *(const float4*)(wb + (kk + dk) * 132 + tx * 8);
        float4 bh = *(const float4*)(wb + (kk + dk) * 132 + tx * 8 + 4);
#pragma unroll
        for (int i = 0; i < 8; i++) {
          float av = (dk == 0) ? a4[i].x : (dk == 1) ? a4[i].y : (dk == 2) ? a4[i].z : a4[i].w;
          acc[i*8+0] += av * bl.x; acc[i*8+1] += av * bl.y;
          acc[i*8+2] += av * bl.z; acc[i*8+3] += av * bl.w;
          acc[i*8+4] += av * bh.x; acc[i*8+5] += av * bh.y;
          acc[i*8+6] += av * bh.z; acc[i*8+7] += av * bh.w;
        }
      }
    }
    __syncthreads();
    if (p < 3) {
      float* wn_ = wp + ((p + 1) & 1) * 4224;
#pragma unroll
      for (int j = 0; j < 4; j++) {
        int kb = kh + 4 * j;
        wn_[(kb+0)*132+rn] = stage[j].x; wn_[(kb+1)*132+rn] = stage[j].y;
        wn_[(kb+2)*132+rn] = stage[j].z; wn_[(kb+3)*132+rn] = stage[j].w;
      }
      __syncthreads();
    }
  }
#pragma unroll
  for (int i = 0; i < 8; i++) {
    float* dst = g_gi + (m0 + ty * 8 + i) * 384 + n0 + tx * 8;
    *(float4*)(dst)     = make_float4(acc[i*8+0], acc[i*8+1], acc[i*8+2], acc[i*8+3]);
    *(float4*)(dst + 4) = make_float4(acc[i*8+4], acc[i*8+5], acc[i*8+6], acc[i*8+7]);
  }
}

__global__ __launch_bounds__(128) void k_act2(const float* __restrict__ x,
                                              const float* __restrict__ w1,
                                              const float* __restrict__ b1,
                                              const float* __restrict__ w2,
                                              const float* __restrict__ b2) {
  extern __shared__ float sm[];
  float* xs  = sm;
  float* w1s = xs + 128 * 132;
  float* w2s = w1s + 64 * 128;
  float* b1s = w2s + 640;
  float* b2s = b1s + 64;
  int tid = threadIdx.x;
  size_t row0 = (size_t)blockIdx.x * 128;
  const float4* xg = (const float4*)(x + row0 * 128);
  for (int i = tid; i < 128 * 32; i += 128) {
    int r = i >> 5, c = i & 31;
    ((float4*)(xs + r * 132))[c] = xg[i];
  }
  for (int i = tid; i < 64 * 32; i += 128) ((float4*)w1s)[i] = ((const float4*)w1)[i];
  for (int i = tid; i < 640; i += 128) w2s[i] = w2[i];
  if (tid < 64) b1s[tid] = b1[tid];
  if (tid < 10) b2s[tid] = b2[tid];
  __syncthreads();
  float acc[64];
#pragma unroll
  for (int u = 0; u < 64; u++) acc[u] = b1s[u];
  const float4* xr = (const float4*)(xs + tid * 132);
  for (int c = 0; c < 32; c++) {
    float4 xv = xr[c];
#pragma unroll
    for (int u = 0; u < 64; u++) {
      float4 wv = ((const float4*)w1s)[u * 32 + c];
      acc[u] += xv.x * wv.x + xv.y * wv.y + xv.z * wv.z + xv.w * wv.w;
    }
  }
#pragma unroll
  for (int u = 0; u < 64; u++) acc[u] = tanhf(acc[u]);
  size_t row = row0 + tid;
  int b = (int)(row >> 9), t = (int)(row & 511);
  const float* gg = g_gum[2 * t + 1] + b * 10;
  float best = -1e30f; int bi = 0;
#pragma unroll
  for (int a = 0; a < 10; a++) {
    float lg = b2s[a];
#pragma unroll
    for (int u = 0; u < 64; u++) lg += acc[u] * w2s[a * 64 + u];
    float v = lg + gg[a];
    if (v > best) { best = v; bi = a; }
  }
  g_act2[t * 256 + b] = bi;
}

// recurrent v4: 128 CTAs x 576 thr, 2 barriers/step.
// warps 0-1 (64 thr): agent-1 logits pipeline. tid>=64: GEMV (gd = tid-64).
__global__ __launch_bounds__(576, 1) void k_recur(const int* __restrict__ mask,
                                                  const float* __restrict__ whh,
                                                  const float* __restrict__ bhh,
                                                  const float* __restrict__ a1w1,
                                                  const float* __restrict__ a1b1,
                                                  const float* __restrict__ a1w2,
                                                  const float* __restrict__ a1b2,
                                                  float* __restrict__ out) {
  extern __shared__ float sm[];
  float* wsp  = sm;                   // 256*132 (w_hh r,z padded)
  float* hs   = wsp + 256 * 132;      // 256
  float* ms   = hs + 256;             // 256
  float* exch = ms + 256;             // 3072
  float* ring = exch + 3072;          // [b2][g3][10][128] = 7680
  float* w1k  = ring + 7680;          // 8192: pairs (k2,u): w1k[(k2*64+u)*2+h]
  float* lgp  = w1k + 8192;           // [warp2][b2][10] = 40
  float* gsm  = lgp + 40;             // [2][20]
  float* bsm  = gsm + 40;             // 12
  int*  asm2  = (int*)(bsm + 12);     // [4]
  int*  ais   = asm2 + 4;             // [4]

  int tid = threadIdx.x;
  int lane = tid & 31, wid = tid >> 5;
  bool isLog = (wid < 2);
  int gd = tid - 64;
  int d = gd & 127, q = gd >> 7;
  bool isOwner = (gd >= 0 && gd < 256);
  int bb = q & 1;
  int b0 = blockIdx.x * 2;
  int bg = b0 + bb;
  float* outh = out + (size_t)Bb * 128;

  for (int i = tid; i < 256 * 128; i += 576)
    wsp[(i >> 7) * 132 + (i & 127)] = whh[i];
  for (int i = tid; i < 7680; i += 576) ring[i] = 0.0f;
  for (int i = tid; i < 8192; i += 576) {
    int hf = i & 1, e = i >> 1, u = e & 63, k2 = e >> 6;
    w1k[i] = a1w1[u * 128 + 2 * k2 + hf];
  }
  if (tid < 10) bsm[tid] = a1b2[tid];

  ull wn[16];
  if (!isLog) {
    const ull* src = (const ull*)(whh + (size_t)(256 + d) * 128 + q * 32);
#pragma unroll
    for (int k = 0; k < 16; k++) wn[k] = src[k];
  }
  float bhn = isOwner ? bhh[256 + d] : 0.0f;

  float w2r[10], b1v = 0.0f;
  if (isLog) {
    int u = wid * 32 + lane;
    b1v = a1b1[u];
#pragma unroll
    for (int a = 0; a < 10; a++) w2r[a] = a1w2[a * 64 + u];
  }

  float h = 0.0f, buf[10];
#pragma unroll
  for (int s9 = 0; s9 < 10; s9++) buf[s9] = 0.0f;

  if (isOwner) {
    size_t rr = ((size_t)bg * 512) * 384;
    float gir = g_gi[rr + d], giz = g_gi[rr + 128 + d], gin = g_gi[rr + 256 + d];
    float r = sigm(gir), z = sigm(giz);
    h = (1.0f - z) * tanhf(gin + r * bhn);
    outh[((size_t)bg * 512) * 128 + d] = h;
  }
  if (wid == 17) {
    if (lane < 20)      gsm[20 + lane] = g_gum[2][(b0 + lane / 10) * 10 + lane % 10];
    else if (lane < 22) asm2[2 + lane - 20] = g_act2[256 + b0 + (lane - 20)];
  }
  __syncthreads();

  for (int t = 1; t < 512; t++) {
    int cur = t & 1, nxt = cur ^ 1;
    float gir = 0, giz = 0, gin = 0;
    if (isOwner) {
      size_t rg = ((size_t)bg * 512 + t) * 384;
      gir = g_gi[rg + d]; giz = g_gi[rg + 128 + d]; gin = g_gi[rg + 256 + d];
      float s = h;
#pragma unroll
      for (int s9 = 0; s9 < 9; s9++) { buf[s9] = buf[s9 + 1]; s += buf[s9]; }
      buf[9] = h;
      hs[bb * 128 + d] = h;
      ms[bb * 128 + d] = s * 0.1f;
    }
    __syncthreads();                                // A
    if (isLog) {
      int u = wid * 32 + lane;
      const ull* w1p = (const ull*)w1k;
      const ull* mA = (const ull*)ms;
      const ull* mB = (const ull*)(ms + 128);
      ull aA0 = 0, aA1 = 0, aB0 = 0, aB1 = 0;
#pragma unroll
      for (int k2 = 0; k2 < 64; k2 += 2) {
        ull w0 = w1p[k2 * 64 + u], w1v = w1p[(k2 + 1) * 64 + u];
        ull m0 = mA[k2], m1 = mA[k2 + 1], n0 = mB[k2], n1 = mB[k2 + 1];
        f2(aA0, w0, m0); f2(aA1, w1v, m1);
        f2(aB0, w0, n0); f2(aB1, w1v, n1);
      }
      float zA = tanhf(hsum(aA0) + hsum(aA1) + b1v);
      float zB = tanhf(hsum(aB0) + hsum(aB1) + b1v);
      float lpA[10], lpB[10];
#pragma unroll
      for (int a = 0; a < 10; a++) { lpA[a] = zA * w2r[a]; lpB[a] = zB * w2r[a]; }
#pragma unroll
      for (int off = 16; off > 0; off >>= 1)
#pragma unroll
        for (int a = 0; a < 10; a++) {
          lpA[a] += __shfl_down_sync(0xffffffffu, lpA[a], off);
          lpB[a] += __shfl_down_sync(0xffffffffu, lpB[a], off);
        }
      if (lane == 0) {
#pragma unroll
        for (int a = 0; a < 10; a++) {
          lgp[wid * 20 + a] = lpA[a];
          lgp[wid * 20 + 10 + a] = lpB[a];
        }
      }
      asm volatile("bar.sync 1, 64;" ::: "memory");
      if (wid == 0 && lane < 2) {
        int b = lane;
        float best = -1e30f; int bi = 0;
#pragma unroll
        for (int a = 0; a < 10; a++) {
          float v = lgp[b * 10 + a] + lgp[20 + b * 10 + a] + bsm[a]
                  + gsm[cur * 20 + b * 10 + a];
          if (v > best) { best = v; bi = a; }
        }
        ais[b] = bi; ais[2 + b] = asm2[cur * 2 + b];
      }
    } else {
      int k0 = q * 32;
      const ulonglong2* wr2 = (const ulonglong2*)(wsp + d * 132 + k0);
      const ulonglong2* wz2 = (const ulonglong2*)(wsp + (d + 128) * 132 + k0);
      const ulonglong2* va = (const ulonglong2*)(hs + k0);
      const ulonglong2* vb = (const ulonglong2*)(hs + 128 + k0);
      ull ar0 = 0, az0 = 0, an0 = 0, ar1 = 0, az1 = 0, an1 = 0;
#pragma unroll
      for (int c = 0; c < 8; c++) {
        ulonglong2 v0 = va[c], v1 = vb[c];
        ulonglong2 w0 = wr2[c], w1v = wz2[c];
        f2(ar0, w0.x, v0.x); f2(ar0, w0.y, v0.y);
        f2(ar1, w0.x, v1.x); f2(ar1, w0.y, v1.y);
        f2(az0, w1v.x, v0.x); f2(az0, w1v.y, v0.y);
        f2(az1, w1v.x, v1.x); f2(az1, w1v.y, v1.y);
        f2(an0, wn[2*c], v0.x); f2(an0, wn[2*c+1], v0.y);
        f2(an1, wn[2*c], v1.x); f2(an1, wn[2*c+1], v1.y);
      }
      exch[((q * 2 + 0) * 3 + 0) * 128 + d] = hsum(ar0);
      exch[((q * 2 + 0) * 3 + 1) * 128 + d] = hsum(az0);
      exch[((q * 2 + 0) * 3 + 2) * 128 + d] = hsum(an0);
      exch[((q * 2 + 1) * 3 + 0) * 128 + d] = hsum(ar1);
      exch[((q * 2 + 1) * 3 + 1) * 128 + d] = hsum(az1);
      exch[((q * 2 + 1) * 3 + 2) * 128 + d] = hsum(an1);
      if (wid == 17 && t < 511) {
        if (lane < 20)
          gsm[nxt * 20 + lane] = g_gum[2 * (t + 1)][(b0 + lane / 10) * 10 + lane % 10];
        else if (lane < 22)
          asm2[nxt * 2 + lane - 20] = g_act2[(t + 1) * 256 + b0 + (lane - 20)];
      }
    }
    __syncthreads();                                // B
    if (isOwner) {
      int aa = ais[bb], a2i = ais[2 + bb];
      int p9 = (t - 1) % 10, s1 = (t + aa) % 10, s2 = (t + a2i) % 10;
      float fsum[3], wh[3];
#pragma unroll
      for (int g = 0; g < 3; g++) {
        fsum[g] = exch[((0 * 2 + bb) * 3 + g) * 128 + d]
                + exch[((1 * 2 + bb) * 3 + g) * 128 + d]
                + exch[((2 * 2 + bb) * 3 + g) * 128 + d]
                + exch[((3 * 2 + bb) * 3 + g) * 128 + d];
      }
#pragma unroll
      for (int g = 0; g < 3; g++) {
        float v1 = (s1 == p9) ? fsum[g] : ring[((bb * 3 + g) * 10 + s1) * 128 + d];
        float v2 = (s2 == p9) ? fsum[g] : ring[((bb * 3 + g) * 10 + s2) * 128 + d];
        wh[g] = 0.25f * (v1 + v2) + 0.5f * fsum[g];
        ring[((bb * 3 + g) * 10 + p9) * 128 + d] = fsum[g];
      }
      float sa = buf[0], sb2 = buf[0];
#pragma unroll
      for (int s9 = 1; s9 < 10; s9++) {
        if (aa == s9) sa = buf[s9];
        if (a2i == s9) sb2 = buf[s9];
      }
      float wtd = 0.25f * (sa + sb2) + 0.5f * h;
      float r = sigm(gir + wh[0]), z = sigm(giz + wh[1]);
      float n = tanhf(gin + r * (wh[2] + bhn));
      h = (1.0f - z) * n + z * wtd;
      outh[((size_t)bg * 512 + t) * 128 + d] = h;
    }
  }

  __syncthreads();
  if (isOwner) {
    int cnt = 0;
    for (int t2 = d; t2 < 512; t2 += 128) cnt += mask[bg * 512 + t2];
    exch[gd] = (float)cnt;
  }
  __syncthreads();
  if (tid < 2) {
    int s = 0;
    for (int i = 0; i < 128; i++) s += (int)exch[tid * 128 + i];
    ais[tid] = s - 1;
  }
  __syncthreads();
  if (isOwner) {
    int li = ais[bb];
    out[bg * 128 + d] = outh[((size_t)bg * 512 + li) * 128 + d];
  }
}

extern "C" void kernel_launch(void* const* d_in, const int* in_sizes, int n_in,
                              void* d_out, int out_size) {
  const float* x    = (const float*)d_in[0];
  const int*   mask = (const int*)d_in[1];
  const float* wih  = (const float*)d_in[2];
  const float* whh  = (const float*)d_in[3];
  const float* bih  = (const float*)d_in[4];
  const float* bhh  = (const float*)d_in[5];
  const float* a1w1 = (const float*)d_in[6];
  const float* a1b1 = (const float*)d_in[7];
  const float* a1w2 = (const float*)d_in[8];
  const float* a1b2 = (const float*)d_in[9];
  const float* a2w1 = (const float*)d_in[10];
  const float* a2b1 = (const float*)d_in[11];
  const float* a2w2 = (const float*)d_in[12];
  const float* a2b2 = (const float*)d_in[13];
  float* out = (float*)d_out;

  const int smem_gi = (128 * 132 + 2 * 32 * 132) * 4;
  const int smem_a2 = (128 * 132 + 64 * 128 + 640 + 64 + 16) * 4;
  const int smem_rc = (256 * 132 + 256 + 256 + 3072 + 7680 + 8192 + 40 + 40 + 12) * 4 + 32;

  cudaFuncSetAttribute(k_gi,    cudaFuncAttributeMaxDynamicSharedMemorySize, smem_gi);
  cudaFuncSetAttribute(k_act2,  cudaFuncAttributeMaxDynamicSharedMemorySize, smem_a2);
  cudaFuncSetAttribute(k_recur, cudaFuncAttributeMaxDynamicSharedMemorySize, smem_rc);

  k_keys<<<4, 256>>>();
  k_gum<<<1024, 256>>>();
  k_act2<<<1024, 128, smem_a2>>>(x, a2w1, a2b1, a2w2, a2b2);
  k_gi<<<dim3(1024, 3), 256, smem_gi>>>(x, wih, bih, bhh);
  k_recur<<<128, 576, smem_rc>>>(mask, whh, bhh, a1w1, a1b1, a1w2, a1b2, out);
}